// round 3
// baseline (speedup 1.0000x reference)
#include <cuda_runtime.h>

#define L_   512
#define B_   128
#define D_   128
#define H_   512
#define OUT_ 5
#define M_   (L_*B_)     // 65536 rows
#define N3_  (3*H_)      // 1536 cols

// Scratch (static device allocations — no cudaMalloc allowed)
__device__ float g_U [(size_t)M_ * N3_];   // 402 MB: U for current layer
__device__ float g_h1[(size_t)M_ * H_];    // 134 MB: layer-0 hidden states
__device__ float g_h2[B_ * H_];            // last-step output of layer 1

// ---------------------------------------------------------------------------
// Packed fp32x2 helpers (Blackwell FFMA2 path — 2x fp32 throughput vs FFMA)
// ---------------------------------------------------------------------------
__device__ __forceinline__ unsigned long long dup2(float x) {
    unsigned long long r;
    asm("mov.b64 %0, {%1, %1};" : "=l"(r) : "f"(x));
    return r;
}
__device__ __forceinline__ void fma2(unsigned long long& d,
                                     unsigned long long a,
                                     unsigned long long b) {
    asm("fma.rn.f32x2 %0, %1, %2, %0;" : "+l"(d) : "l"(a), "l"(b));
}

// ---------------------------------------------------------------------------
// SGEMM: C[M x N] = A[M x K] @ B[K x N], fp32, f32x2 packed inner loop.
// BM=BN=128, BK=16, 256 threads, 8x8 per thread (cols as 4 f32x2 pairs,
// pair j lives at column j*32 + tx*2 -> conflict-free LDS.64 on Bs).
// ---------------------------------------------------------------------------
template<int K>
__global__ __launch_bounds__(256, 2)
void sgemm_f32x2(const float* __restrict__ A, const float* __restrict__ Bw,
                 float* __restrict__ C, int N)
{
    __shared__ unsigned long long As2[16][129];  // duplicated A pairs, padded
    __shared__ float Bs[16][128];

    const int tid = threadIdx.x;
    const int tx  = tid & 15;    // n-group
    const int ty  = tid >> 4;    // m-group
    const int rowBase = blockIdx.y << 7;
    const int colBase = blockIdx.x << 7;

    const int arow = tid >> 2;   // 0..63 (A tile row, +64 second pass)
    const int ak4  = tid & 3;    // which float4 along k
    const int bk   = tid >> 5;   // 0..7  (B tile k-row, +8 second pass)
    const int bc4  = tid & 31;   // which float4 along n

    unsigned long long acc[8][4];
    #pragma unroll
    for (int i = 0; i < 8; i++)
        #pragma unroll
        for (int j = 0; j < 4; j++) acc[i][j] = 0ULL;

    const float* Ab = A + (size_t)rowBase * K;
    const float* Bb = Bw + colBase;

    for (int kt = 0; kt < K; kt += 16) {
        #pragma unroll
        for (int r = 0; r < 2; r++) {
            const int m = arow + r * 64;
            const float4 av = *reinterpret_cast<const float4*>(
                Ab + (size_t)m * K + kt + ak4 * 4);
            As2[ak4*4+0][m] = dup2(av.x);
            As2[ak4*4+1][m] = dup2(av.y);
            As2[ak4*4+2][m] = dup2(av.z);
            As2[ak4*4+3][m] = dup2(av.w);
        }
        #pragma unroll
        for (int r = 0; r < 2; r++) {
            const int k = bk + r * 8;
            *reinterpret_cast<float4*>(&Bs[k][bc4*4]) =
                *reinterpret_cast<const float4*>(Bb + (size_t)(kt + k) * N + bc4*4);
        }
        __syncthreads();

        #pragma unroll
        for (int k = 0; k < 16; k++) {
            unsigned long long ra[8], rb[4];
            #pragma unroll
            for (int i = 0; i < 8; i++) ra[i] = As2[k][ty*8 + i];
            const unsigned long long* bp =
                reinterpret_cast<const unsigned long long*>(&Bs[k][0]);
            #pragma unroll
            for (int j = 0; j < 4; j++) rb[j] = bp[j*16 + tx];
            #pragma unroll
            for (int i = 0; i < 8; i++)
                #pragma unroll
                for (int j = 0; j < 4; j++) fma2(acc[i][j], ra[i], rb[j]);
        }
        __syncthreads();
    }

    #pragma unroll
    for (int i = 0; i < 8; i++) {
        float* crow = C + (size_t)(rowBase + ty*8 + i) * N + colBase;
        #pragma unroll
        for (int j = 0; j < 4; j++) {
            float lo, hi;
            asm("mov.b64 {%0, %1}, %2;" : "=f"(lo), "=f"(hi) : "l"(acc[i][j]));
            *reinterpret_cast<float2*>(crow + j*32 + tx*2) = make_float2(lo, hi);
        }
    }
}

// ---------------------------------------------------------------------------
// SRU recurrence: one thread per (b, h) channel, sequential over t.
// Loads are address-independent of the carried state -> compiler can batch.
// ---------------------------------------------------------------------------
__device__ __forceinline__ float sigmoidf_(float z) {
    return 1.f / (1.f + __expf(-z));
}

__global__ void rec_kernel(const float* __restrict__ U,
                           const float* __restrict__ v,
                           const float* __restrict__ bias,
                           float* __restrict__ hout, int writeAll)
{
    const int tid = blockIdx.x * blockDim.x + threadIdx.x;  // 0..B*H-1
    const int b = tid >> 9;          // / H_
    const int h = tid & (H_ - 1);
    const float vf = v[h],      vr = v[H_ + h];
    const float bf = bias[h],   br = bias[H_ + h];
    float c = 0.f;
    float hlast = 0.f;
    #pragma unroll 4
    for (int t = 0; t < L_; t++) {
        const size_t base = ((size_t)t * B_ + b) * N3_;
        const float u0 = U[base + h];
        const float u1 = U[base + H_ + h];
        const float u2 = U[base + 2*H_ + h];
        const float f = sigmoidf_(u1 + vf * c + bf);
        const float r = sigmoidf_(u2 + vr * c + br);
        c = f * c + (1.f - f) * u0;
        const float hv = r * c;
        if (writeAll) hout[((size_t)t * B_ + b) * H_ + h] = hv;
        hlast = hv;
    }
    if (!writeAll) hout[b * H_ + h] = hlast;
}

// ---------------------------------------------------------------------------
// Final FC: out[b,o] = sum_h h2[b,h] * fc_w[o,h] + fc_b[o]   (128 x 5)
// One warp per batch row.
// ---------------------------------------------------------------------------
__global__ void fc_kernel(const float* __restrict__ h2,
                          const float* __restrict__ w,
                          const float* __restrict__ bias,
                          float* __restrict__ out)
{
    const int gtid = blockIdx.x * blockDim.x + threadIdx.x;
    const int warp = gtid >> 5;
    const int lane = gtid & 31;
    if (warp >= B_) return;
    #pragma unroll
    for (int o = 0; o < OUT_; o++) {
        float s = 0.f;
        for (int h = lane; h < H_; h += 32)
            s += h2[warp * H_ + h] * w[o * H_ + h];
        #pragma unroll
        for (int off = 16; off > 0; off >>= 1)
            s += __shfl_down_sync(0xffffffffu, s, off);
        if (lane == 0) out[warp * OUT_ + o] = s + bias[o];
    }
}

// ---------------------------------------------------------------------------
extern "C" void kernel_launch(void* const* d_in, const int* in_sizes, int n_in,
                              void* d_out, int out_size)
{
    const float* x   = (const float*)d_in[0];
    const float* W0  = (const float*)d_in[1];
    const float* v0  = (const float*)d_in[2];
    const float* b0  = (const float*)d_in[3];
    const float* W1  = (const float*)d_in[4];
    const float* v1  = (const float*)d_in[5];
    const float* b1  = (const float*)d_in[6];
    const float* fcw = (const float*)d_in[7];
    const float* fcb = (const float*)d_in[8];
    float* out = (float*)d_out;

    float *pU, *pH1, *pH2;
    cudaGetSymbolAddress((void**)&pU,  g_U);
    cudaGetSymbolAddress((void**)&pH1, g_h1);
    cudaGetSymbolAddress((void**)&pH2, g_h2);

    const dim3 gemmGrid(N3_ / 128, M_ / 128);   // (12, 512)

    // Layer 0
    sgemm_f32x2<D_><<<gemmGrid, 256>>>(x, W0, pU, N3_);
    rec_kernel<<<(B_ * H_) / 256, 256>>>(pU, v0, b0, pH1, 1);

    // Layer 1 (reuse g_U)
    sgemm_f32x2<H_><<<gemmGrid, 256>>>(pH1, W1, pU, N3_);
    rec_kernel<<<(B_ * H_) / 256, 256>>>(pU, v1, b1, pH2, 0);

    // Head
    fc_kernel<<<(B_ * 32 + 255) / 256, 256>>>(pH2, fcw, fcb, out);
}

// round 6
// speedup vs baseline: 2.7207x; 2.7207x over previous
#include <cuda_runtime.h>
#include <cuda_bf16.h>
#include <cstdint>

#define L_   512
#define B_   128
#define D_   128
#define H_   512
#define OUT_ 5
#define M_   (L_*B_)     // 65536 rows
#define N3_  (3*H_)      // 1536 cols

// ---------------------------------------------------------------------------
// Static device scratch (no cudaMalloc allowed)
// ---------------------------------------------------------------------------
__device__ float         g_U   [(size_t)M_ * N3_];          // 402 MB
__device__ __nv_bfloat16 g_Ahi [(size_t)M_ * H_];           // 64 MB (x split / h1 hi)
__device__ __nv_bfloat16 g_Alo [(size_t)M_ * H_];           // 64 MB (x split / h1 lo)
__device__ __nv_bfloat16 g_BtHi[(size_t)N3_ * H_];          // 1.5 MB
__device__ __nv_bfloat16 g_BtLo[(size_t)N3_ * H_];
__device__ float         g_h2  [B_ * H_];

// ---------------------------------------------------------------------------
// Helpers (base-ISA only: ldmatrix / mma.sync / cp.async — no 'a' features)
// ---------------------------------------------------------------------------
__device__ __forceinline__ uint32_t smem_to_u32(const void* p) {
    uint32_t a;
    asm("{ .reg .u64 t; cvta.to.shared.u64 t, %1; cvt.u32.u64 %0, t; }" : "=r"(a) : "l"(p));
    return a;
}
#define SW128(bo) ((bo) ^ (((bo) >> 3) & 0x70))

__device__ __forceinline__ void cp_async16(uint32_t dst, const void* src) {
    asm volatile("cp.async.cg.shared.global [%0], [%1], 16;" :: "r"(dst), "l"(src) : "memory");
}
__device__ __forceinline__ void cp_commit() {
    asm volatile("cp.async.commit_group;" ::: "memory");
}
template<int N>
__device__ __forceinline__ void cp_wait() {
    asm volatile("cp.async.wait_group %0;" :: "n"(N) : "memory");
}
__device__ __forceinline__ void ldm_x4(uint32_t& r0, uint32_t& r1, uint32_t& r2, uint32_t& r3,
                                       uint32_t addr) {
    asm volatile("ldmatrix.sync.aligned.m8n8.x4.shared.b16 {%0,%1,%2,%3}, [%4];"
                 : "=r"(r0), "=r"(r1), "=r"(r2), "=r"(r3) : "r"(addr));
}
__device__ __forceinline__ void mma_bf16(float* c, const uint32_t* a, const uint32_t* b) {
    asm volatile(
        "mma.sync.aligned.m16n8k16.row.col.f32.bf16.bf16.f32 "
        "{%0,%1,%2,%3}, {%4,%5,%6,%7}, {%8,%9}, {%0,%1,%2,%3};"
        : "+f"(c[0]), "+f"(c[1]), "+f"(c[2]), "+f"(c[3])
        : "r"(a[0]), "r"(a[1]), "r"(a[2]), "r"(a[3]), "r"(b[0]), "r"(b[1]));
}

// ---------------------------------------------------------------------------
// GEMM: C[M x N3] = (Ahi+Alo)[M x K] @ (Bhi+Blo)^T[N3 x K], fp32-via-3xbf16.
// CTA tile 128x128, BK=64, 8 warps (2m x 4n), warp tile 64x32.
// SMEM: per stage Ahi|Alo|Bhi|Blo, each 128x64 bf16 (16KB) SW128-swizzled.
// Double-buffered cp.async pipeline.
// ---------------------------------------------------------------------------
#define TILE_B   16384                 // one 128x64 bf16 tile
#define OFF_AHI  0
#define OFF_ALO  (TILE_B)
#define OFF_BHI  (2*TILE_B)
#define OFF_BLO  (3*TILE_B)
#define STAGE_B  (4*TILE_B)            // 64 KB
#define GEMM_SMEM (2*STAGE_B)          // 128 KB

template<int KTOT>
__device__ __forceinline__ void load_stage(uint32_t sb, int buf, int kt,
    const __nv_bfloat16* __restrict__ Ahi, const __nv_bfloat16* __restrict__ Alo,
    const __nv_bfloat16* __restrict__ Bhi, const __nv_bfloat16* __restrict__ Blo,
    int rowBase, int colBase, int tid)
{
    const uint32_t base = sb + buf * STAGE_B;
    const int kOff = kt * 64;
    #pragma unroll
    for (int i = 0; i < 4; i++) {                 // A tiles: 1024 chunks of 16B
        const int ci = tid + i * 256;
        const int row = ci >> 3, c8 = ci & 7;
        const size_t g = (size_t)(rowBase + row) * KTOT + kOff + c8 * 8;
        const uint32_t so = SW128((uint32_t)(row * 128 + c8 * 16));
        cp_async16(base + OFF_AHI + so, Ahi + g);
        cp_async16(base + OFF_ALO + so, Alo + g);
    }
    #pragma unroll
    for (int i = 0; i < 4; i++) {                 // B tiles
        const int ci = tid + i * 256;
        const int row = ci >> 3, c8 = ci & 7;
        const size_t g = (size_t)(colBase + row) * KTOT + kOff + c8 * 8;
        const uint32_t so = SW128((uint32_t)(row * 128 + c8 * 16));
        cp_async16(base + OFF_BHI + so, Bhi + g);
        cp_async16(base + OFF_BLO + so, Blo + g);
    }
}

__device__ __forceinline__ void compute_stage(uint32_t sb, int buf,
    int warp_m, int warp_n, int lane, float acc[4][4][4])
{
    const uint32_t base = sb + buf * STAGE_B;
    #pragma unroll
    for (int k16 = 0; k16 < 4; k16++) {
        // A fragments: 4 m-atoms x (hi,lo)
        uint32_t ahi[4][4], alo[4][4];
        {
            const int m = warp_m * 64 + (lane & 15);
            const int kc = k16 * 2 + (lane >> 4);
            #pragma unroll
            for (int ma = 0; ma < 4; ma++) {
                const uint32_t so = SW128((uint32_t)((m + ma * 16) * 128 + kc * 16));
                ldm_x4(ahi[ma][0], ahi[ma][1], ahi[ma][2], ahi[ma][3], base + OFF_AHI + so);
                ldm_x4(alo[ma][0], alo[ma][1], alo[ma][2], alo[ma][3], base + OFF_ALO + so);
            }
        }
        // B fragments: 4 n8-atoms x (hi,lo)
        uint32_t bhi[4][2], blo[4][2];
        {
            const int g = lane >> 3, rr = lane & 7;
            #pragma unroll
            for (int ng = 0; ng < 2; ng++) {
                const int n = warp_n * 32 + ng * 16 + (g >> 1) * 8 + rr;
                const uint32_t so = SW128((uint32_t)(n * 128 + (k16 * 2 + (g & 1)) * 16));
                uint32_t r0, r1, r2, r3;
                ldm_x4(r0, r1, r2, r3, base + OFF_BHI + so);
                bhi[ng*2][0] = r0; bhi[ng*2][1] = r1; bhi[ng*2+1][0] = r2; bhi[ng*2+1][1] = r3;
                ldm_x4(r0, r1, r2, r3, base + OFF_BLO + so);
                blo[ng*2][0] = r0; blo[ng*2][1] = r1; blo[ng*2+1][0] = r2; blo[ng*2+1][1] = r3;
            }
        }
        #pragma unroll
        for (int ma = 0; ma < 4; ma++)
            #pragma unroll
            for (int na = 0; na < 4; na++) {
                mma_bf16(acc[ma][na], ahi[ma], bhi[na]);
                mma_bf16(acc[ma][na], ahi[ma], blo[na]);
                mma_bf16(acc[ma][na], alo[ma], bhi[na]);
            }
    }
}

template<int KTOT>
__global__ __launch_bounds__(256, 1)
void gemm_hmma(const __nv_bfloat16* __restrict__ Ahi,
               const __nv_bfloat16* __restrict__ Alo,
               const __nv_bfloat16* __restrict__ Bhi,
               const __nv_bfloat16* __restrict__ Blo,
               float* __restrict__ C)
{
    extern __shared__ char smem[];
    const uint32_t sb = smem_to_u32(smem);
    const int tid = threadIdx.x, wid = tid >> 5, lane = tid & 31;
    const int warp_m = wid & 1, warp_n = wid >> 1;
    const int rowBase = blockIdx.y << 7;
    const int colBase = blockIdx.x << 7;
    constexpr int KT = KTOT / 64;

    float acc[4][4][4];
    #pragma unroll
    for (int i = 0; i < 4; i++)
        #pragma unroll
        for (int j = 0; j < 4; j++)
            #pragma unroll
            for (int k = 0; k < 4; k++) acc[i][j][k] = 0.f;

    load_stage<KTOT>(sb, 0, 0, Ahi, Alo, Bhi, Blo, rowBase, colBase, tid);
    cp_commit();

    #pragma unroll 1
    for (int kt = 0; kt < KT; kt++) {
        if (kt + 1 < KT) {
            load_stage<KTOT>(sb, (kt + 1) & 1, kt + 1, Ahi, Alo, Bhi, Blo,
                             rowBase, colBase, tid);
            cp_commit();
            cp_wait<1>();
        } else {
            cp_wait<0>();
        }
        __syncthreads();
        compute_stage(sb, kt & 1, warp_m, warp_n, lane, acc);
        __syncthreads();
    }

    // Epilogue: direct fp32 stores (float2 per atom row-half)
    const int mBase = rowBase + warp_m * 64 + (lane >> 2);
    const int nBase = colBase + warp_n * 32 + (lane & 3) * 2;
    #pragma unroll
    for (int ma = 0; ma < 4; ma++) {
        #pragma unroll
        for (int na = 0; na < 4; na++) {
            const int m = mBase + ma * 16;
            const int n = nBase + na * 8;
            *reinterpret_cast<float2*>(C + (size_t)m * N3_ + n) =
                make_float2(acc[ma][na][0], acc[ma][na][1]);
            *reinterpret_cast<float2*>(C + (size_t)(m + 8) * N3_ + n) =
                make_float2(acc[ma][na][2], acc[ma][na][3]);
        }
    }
}

// ---------------------------------------------------------------------------
// Split fp32 -> bf16 hi/lo (elementwise, float4-vectorized)
// ---------------------------------------------------------------------------
__global__ void split_kernel(const float* __restrict__ src,
                             __nv_bfloat16* __restrict__ hi,
                             __nv_bfloat16* __restrict__ lo, int n4)
{
    const int i = blockIdx.x * blockDim.x + threadIdx.x;
    if (i >= n4) return;
    const float4 v = reinterpret_cast<const float4*>(src)[i];
    float f[4] = {v.x, v.y, v.z, v.w};
    __nv_bfloat16 h[4], l[4];
    #pragma unroll
    for (int j = 0; j < 4; j++) {
        h[j] = __float2bfloat16(f[j]);
        l[j] = __float2bfloat16(f[j] - __bfloat162float(h[j]));
    }
    __nv_bfloat162* hp = reinterpret_cast<__nv_bfloat162*>(hi + 4 * (size_t)i);
    __nv_bfloat162* lp = reinterpret_cast<__nv_bfloat162*>(lo + 4 * (size_t)i);
    hp[0] = __nv_bfloat162(h[0], h[1]); hp[1] = __nv_bfloat162(h[2], h[3]);
    lp[0] = __nv_bfloat162(l[0], l[1]); lp[1] = __nv_bfloat162(l[2], l[3]);
}

// Transpose + split: W[K, N3] fp32 -> hiT/loT[N3, K] bf16
__global__ void splitT_kernel(const float* __restrict__ W,
                              __nv_bfloat16* __restrict__ hiT,
                              __nv_bfloat16* __restrict__ loT, int K)
{
    const int idx = blockIdx.x * blockDim.x + threadIdx.x;
    if (idx >= K * N3_) return;
    const int k = idx / N3_, n = idx % N3_;
    const float f = W[idx];
    const __nv_bfloat16 h = __float2bfloat16(f);
    hiT[(size_t)n * K + k] = h;
    loT[(size_t)n * K + k] = __float2bfloat16(f - __bfloat162float(h));
}

// ---------------------------------------------------------------------------
// SRU recurrence, software-pipelined (prefetch next 4-t batch before compute)
// ---------------------------------------------------------------------------
__device__ __forceinline__ float sigmoidf_(float z) { return 1.f / (1.f + __expf(-z)); }

__global__ __launch_bounds__(256)
void rec0_kernel(const float* __restrict__ U, const float* __restrict__ v,
                 const float* __restrict__ bias,
                 __nv_bfloat16* __restrict__ hHi, __nv_bfloat16* __restrict__ hLo)
{
    const int tid = blockIdx.x * blockDim.x + threadIdx.x;
    const int b = tid >> 9, h = tid & (H_ - 1);
    const float vf = v[h], vr = v[H_ + h];
    const float bf = bias[h], br = bias[H_ + h];
    float c = 0.f;
    float a0[4], a1[4], a2[4];
    #pragma unroll
    for (int i = 0; i < 4; i++) {
        const size_t base = ((size_t)i * B_ + b) * N3_ + h;
        a0[i] = __ldcs(U + base); a1[i] = __ldcs(U + base + H_); a2[i] = __ldcs(U + base + 2*H_);
    }
    for (int t0 = 0; t0 < L_; t0 += 4) {
        float n0[4] = {0,0,0,0}, n1[4] = {0,0,0,0}, n2[4] = {0,0,0,0};
        if (t0 + 4 < L_) {
            #pragma unroll
            for (int i = 0; i < 4; i++) {
                const size_t base = ((size_t)(t0 + 4 + i) * B_ + b) * N3_ + h;
                n0[i] = __ldcs(U + base); n1[i] = __ldcs(U + base + H_); n2[i] = __ldcs(U + base + 2*H_);
            }
        }
        #pragma unroll
        for (int i = 0; i < 4; i++) {
            const float f = sigmoidf_(a1[i] + vf * c + bf);
            const float r = sigmoidf_(a2[i] + vr * c + br);
            c = f * c + (1.f - f) * a0[i];
            const float hv = r * c;
            const __nv_bfloat16 hb = __float2bfloat16(hv);
            const size_t o = ((size_t)(t0 + i) * B_ + b) * H_ + h;
            hHi[o] = hb;
            hLo[o] = __float2bfloat16(hv - __bfloat162float(hb));
        }
        #pragma unroll
        for (int i = 0; i < 4; i++) { a0[i] = n0[i]; a1[i] = n1[i]; a2[i] = n2[i]; }
    }
}

__global__ __launch_bounds__(256)
void rec1_kernel(const float* __restrict__ U, const float* __restrict__ v,
                 const float* __restrict__ bias, float* __restrict__ hout)
{
    const int tid = blockIdx.x * blockDim.x + threadIdx.x;
    const int b = tid >> 9, h = tid & (H_ - 1);
    const float vf = v[h], vr = v[H_ + h];
    const float bf = bias[h], br = bias[H_ + h];
    float c = 0.f, hlast = 0.f;
    float a0[4], a1[4], a2[4];
    #pragma unroll
    for (int i = 0; i < 4; i++) {
        const size_t base = ((size_t)i * B_ + b) * N3_ + h;
        a0[i] = __ldcs(U + base); a1[i] = __ldcs(U + base + H_); a2[i] = __ldcs(U + base + 2*H_);
    }
    for (int t0 = 0; t0 < L_; t0 += 4) {
        float n0[4] = {0,0,0,0}, n1[4] = {0,0,0,0}, n2[4] = {0,0,0,0};
        if (t0 + 4 < L_) {
            #pragma unroll
            for (int i = 0; i < 4; i++) {
                const size_t base = ((size_t)(t0 + 4 + i) * B_ + b) * N3_ + h;
                n0[i] = __ldcs(U + base); n1[i] = __ldcs(U + base + H_); n2[i] = __ldcs(U + base + 2*H_);
            }
        }
        #pragma unroll
        for (int i = 0; i < 4; i++) {
            const float f = sigmoidf_(a1[i] + vf * c + bf);
            const float r = sigmoidf_(a2[i] + vr * c + br);
            c = f * c + (1.f - f) * a0[i];
            hlast = r * c;
        }
        #pragma unroll
        for (int i = 0; i < 4; i++) { a0[i] = n0[i]; a1[i] = n1[i]; a2[i] = n2[i]; }
    }
    hout[b * H_ + h] = hlast;
}

// ---------------------------------------------------------------------------
// Final FC: out[b,o] = h2[b,:] . fc_w[o,:] + fc_b[o]
// ---------------------------------------------------------------------------
__global__ void fc_kernel(const float* __restrict__ h2, const float* __restrict__ w,
                          const float* __restrict__ bias, float* __restrict__ out)
{
    const int gtid = blockIdx.x * blockDim.x + threadIdx.x;
    const int warp = gtid >> 5, lane = gtid & 31;
    if (warp >= B_) return;
    #pragma unroll
    for (int o = 0; o < OUT_; o++) {
        float s = 0.f;
        for (int h = lane; h < H_; h += 32) s += h2[warp * H_ + h] * w[o * H_ + h];
        #pragma unroll
        for (int off = 16; off > 0; off >>= 1) s += __shfl_down_sync(0xffffffffu, s, off);
        if (lane == 0) out[warp * OUT_ + o] = s + bias[o];
    }
}

// ---------------------------------------------------------------------------
extern "C" void kernel_launch(void* const* d_in, const int* in_sizes, int n_in,
                              void* d_out, int out_size)
{
    const float* x   = (const float*)d_in[0];
    const float* W0  = (const float*)d_in[1];
    const float* v0  = (const float*)d_in[2];
    const float* b0  = (const float*)d_in[3];
    const float* W1  = (const float*)d_in[4];
    const float* v1  = (const float*)d_in[5];
    const float* b1  = (const float*)d_in[6];
    const float* fcw = (const float*)d_in[7];
    const float* fcb = (const float*)d_in[8];
    float* out = (float*)d_out;

    float *pU, *pH2;
    __nv_bfloat16 *pAhi, *pAlo, *pBhi, *pBlo;
    cudaGetSymbolAddress((void**)&pU,   g_U);
    cudaGetSymbolAddress((void**)&pAhi, g_Ahi);
    cudaGetSymbolAddress((void**)&pAlo, g_Alo);
    cudaGetSymbolAddress((void**)&pBhi, g_BtHi);
    cudaGetSymbolAddress((void**)&pBlo, g_BtLo);
    cudaGetSymbolAddress((void**)&pH2,  g_h2);

    cudaFuncSetAttribute(gemm_hmma<128>, cudaFuncAttributeMaxDynamicSharedMemorySize, GEMM_SMEM);
    cudaFuncSetAttribute(gemm_hmma<512>, cudaFuncAttributeMaxDynamicSharedMemorySize, GEMM_SMEM);

    const dim3 gemmGrid(N3_ / 128, M_ / 128);   // (12, 512) — n fast for A L2 reuse

    // ---- Layer 0 ----
    split_kernel<<<(M_ * D_ / 4 + 255) / 256, 256>>>(x, pAhi, pAlo, M_ * D_ / 4);
    splitT_kernel<<<(D_ * N3_ + 255) / 256, 256>>>(W0, pBhi, pBlo, D_);
    gemm_hmma<128><<<gemmGrid, 256, GEMM_SMEM>>>(pAhi, pAlo, pBhi, pBlo, pU);
    rec0_kernel<<<(B_ * H_) / 256, 256>>>(pU, v0, b0, pAhi, pAlo);  // h1 directly as bf16 hi/lo

    // ---- Layer 1 ----
    splitT_kernel<<<(H_ * N3_ + 255) / 256, 256>>>(W1, pBhi, pBlo, H_);
    gemm_hmma<512><<<gemmGrid, 256, GEMM_SMEM>>>(pAhi, pAlo, pBhi, pBlo, pU);
    rec1_kernel<<<(B_ * H_) / 256, 256>>>(pU, v1, b1, pH2);

    // ---- Head ----
    fc_kernel<<<(B_ * 32 + 255) / 256, 256>>>(pH2, fcw, fcb, out);
}